// round 1
// baseline (speedup 1.0000x reference)
#include <cuda_runtime.h>

#define Bsz   16
#define Cch   32
#define Himg  256
#define Wimg  256

#define TILE_H 16
#define TILE_W 32
#define HALO_H 18
#define HALO_W 34

#define THREADS 512

#define WS_STRIDE 33                       // 32 co + 1 pad (bank-conflict-free)
#define XS_ELEMS  (Cch * HALO_H * HALO_W)  // 19584
#define WS_ELEMS  (Cch * 9 * WS_STRIDE)    // 9504
#define SMEM_BYTES ((XS_ELEMS + WS_ELEMS) * 4)

// Scratch for the intermediate activation h (pass1 output / pass2 input).
__device__ float g_h[Bsz * Cch * Himg * Wimg];

template <bool SECOND>
__global__ __launch_bounds__(THREADS, 1)
void moe_conv_kernel(const float* __restrict__ x,     // original input [B,C,H,W]
                     const float* __restrict__ w,     // [C,C,3,3] OIHW
                     const float* __restrict__ bias,  // [C]
                     const float* __restrict__ gate,  // [B,C]
                     float* __restrict__ out)         // final output (pass2 only)
{
    extern __shared__ float sm[];
    float* xs = sm;              // [ci][row][col] : Cch x HALO_H x HALO_W
    float* ws = sm + XS_ELEMS;   // [ci*9+tap][co] stride WS_STRIDE

    const int bx  = blockIdx.x;          // 0..7   (W tiles)
    const int by  = blockIdx.y;          // 0..15  (H tiles)
    const int bb  = blockIdx.z;          // 0..15  (batch)
    const int tid = threadIdx.x;

    const int x0 = bx * TILE_W;
    const int y0 = by * TILE_H;

    // ---- load weights, transposed to [ci*9+tap][co] ----
    #pragma unroll 1
    for (int i = tid; i < Cch * Cch * 9; i += THREADS) {
        int co  = i / (Cch * 9);
        int rem = i - co * (Cch * 9);    // ci*9 + tap
        ws[rem * WS_STRIDE + co] = w[i];
    }

    // ---- load input tile (x for pass1, h for pass2) with zero halo ----
    const float* inb = (SECOND ? g_h : x) + (size_t)bb * Cch * Himg * Wimg;
    #pragma unroll 1
    for (int i = tid; i < XS_ELEMS; i += THREADS) {
        int ci = i / (HALO_H * HALO_W);
        int r  = (i / HALO_W) % HALO_H;
        int c  = i % HALO_W;
        int gy = y0 + r - 1;
        int gx = x0 + c - 1;
        float v = 0.0f;
        if ((unsigned)gy < (unsigned)Himg && (unsigned)gx < (unsigned)Wimg)
            v = inb[(size_t)ci * (Himg * Wimg) + gy * Wimg + gx];
        xs[i] = v;
    }
    __syncthreads();

    // ---- thread tile: 4 output channels x 8 pixels ----
    const int cg  = tid & 7;         // co group (8 groups of 4)
    const int pg  = tid >> 3;        // pixel group (64 groups of 8)
    const int r   = pg >> 2;         // tile row 0..15
    const int cb  = (pg & 3) * 8;    // tile col base 0/8/16/24
    const int co0 = cg * 4;

    float acc[4][8];
    #pragma unroll
    for (int a = 0; a < 4; a++)
        #pragma unroll
        for (int j = 0; j < 8; j++)
            acc[a][j] = 0.0f;

    #pragma unroll 2
    for (int ci = 0; ci < Cch; ci++) {
        const float* xci = xs + ci * (HALO_H * HALO_W);
        #pragma unroll
        for (int dy = 0; dy < 3; dy++) {
            const float* xr = xci + (r + dy) * HALO_W + cb;
            float xv[10];
            #pragma unroll
            for (int k = 0; k < 10; k++) xv[k] = xr[k];

            #pragma unroll
            for (int dx = 0; dx < 3; dx++) {
                const float* wp = ws + (ci * 9 + dy * 3 + dx) * WS_STRIDE + co0;
                float w0 = wp[0], w1 = wp[1], w2 = wp[2], w3 = wp[3];
                #pragma unroll
                for (int j = 0; j < 8; j++) {
                    float xj = xv[dx + j];
                    acc[0][j] += w0 * xj;
                    acc[1][j] += w1 * xj;
                    acc[2][j] += w2 * xj;
                    acc[3][j] += w3 * xj;
                }
            }
        }
    }

    // ---- epilogue: bias, gate, relu, (+residual), store ----
    const int oy = y0 + r;
    const int ox = x0 + cb;
    float* dst = SECOND ? out : g_h;

    #pragma unroll
    for (int a = 0; a < 4; a++) {
        int co = co0 + a;
        float bi = bias[co];
        float g  = gate[bb * Cch + co];
        g = (g > 0.0f) ? g : 0.0f;

        size_t base = (((size_t)bb * Cch + co) * Himg + oy) * Wimg + ox;

        float t[8];
        #pragma unroll
        for (int j = 0; j < 8; j++) {
            float v = (acc[a][j] + bi) * g;
            t[j] = (v > 0.0f) ? v : 0.0f;
        }

        if (SECOND) {
            const float4* rx = reinterpret_cast<const float4*>(x + base);
            float4 r0 = rx[0], r1 = rx[1];
            t[0] += r0.x; t[1] += r0.y; t[2] += r0.z; t[3] += r0.w;
            t[4] += r1.x; t[5] += r1.y; t[6] += r1.z; t[7] += r1.w;
        }

        float4* op = reinterpret_cast<float4*>(dst + base);
        op[0] = make_float4(t[0], t[1], t[2], t[3]);
        op[1] = make_float4(t[4], t[5], t[6], t[7]);
    }
}

extern "C" void kernel_launch(void* const* d_in, const int* in_sizes, int n_in,
                              void* d_out, int out_size)
{
    const float* x    = (const float*)d_in[0];
    const float* gate = (const float*)d_in[1];
    const float* w1   = (const float*)d_in[2];
    const float* b1   = (const float*)d_in[3];
    const float* w2   = (const float*)d_in[4];
    const float* b2   = (const float*)d_in[5];
    float*       out  = (float*)d_out;
    (void)in_sizes; (void)n_in; (void)out_size;

    cudaFuncSetAttribute(moe_conv_kernel<false>,
                         cudaFuncAttributeMaxDynamicSharedMemorySize, SMEM_BYTES);
    cudaFuncSetAttribute(moe_conv_kernel<true>,
                         cudaFuncAttributeMaxDynamicSharedMemorySize, SMEM_BYTES);

    dim3 grid(Wimg / TILE_W, Himg / TILE_H, Bsz);   // 8 x 16 x 16 = 2048 CTAs

    // pass 1: h = relu((conv(x,w1)+b1)*g)   -> g_h
    moe_conv_kernel<false><<<grid, THREADS, SMEM_BYTES>>>(x, w1, b1, gate, nullptr);
    // pass 2: out = relu((conv(h,w2)+b2)*g) + x
    moe_conv_kernel<true><<<grid, THREADS, SMEM_BYTES>>>(x, w2, b2, gate, out);
}

// round 2
// speedup vs baseline: 1.0123x; 1.0123x over previous
#include <cuda_runtime.h>

#define Bsz   16
#define Cch   32
#define Himg  256
#define Wimg  256

#define TILE_H 16
#define TILE_W 32
#define HALO_H 18
#define HALO_W 36   // padded to keep rows 16B-aligned (only 34 cols meaningful)

#define THREADS 512

#define WS_STRIDE 36                       // 32 co + pad; multiple of 4 -> 16B-aligned co groups
#define XS_ELEMS  (Cch * HALO_H * HALO_W)  // 20736 floats
#define WS_ELEMS  (Cch * 9 * WS_STRIDE)    // 10368 floats
#define SMEM_BYTES ((XS_ELEMS + WS_ELEMS) * 4)   // ~124.4 KB

// Scratch for the intermediate activation h (pass1 output / pass2 input).
__device__ float g_h[Bsz * Cch * Himg * Wimg];

// ---- f32x2 packed helpers (sm_103a dual-fp32 pipe) ----
__device__ __forceinline__ unsigned long long pack2_dup(float v) {
    unsigned long long r;
    asm("mov.b64 %0, {%1, %1};" : "=l"(r) : "f"(v));
    return r;
}
__device__ __forceinline__ void fma2(unsigned long long& d,
                                     unsigned long long a,
                                     unsigned long long b) {
    asm("fma.rn.f32x2 %0, %1, %2, %0;" : "+l"(d) : "l"(a), "l"(b));
}
__device__ __forceinline__ void unpack2(float& lo, float& hi, unsigned long long v) {
    asm("mov.b64 {%0, %1}, %2;" : "=f"(lo), "=f"(hi) : "l"(v));
}

template <bool SECOND>
__global__ __launch_bounds__(THREADS, 1)
void moe_conv_kernel(const float* __restrict__ x,     // original input [B,C,H,W]
                     const float* __restrict__ w,     // [C,C,3,3] OIHW
                     const float* __restrict__ bias,  // [C]
                     const float* __restrict__ gate,  // [B,C]
                     float* __restrict__ out)         // final output (pass2 only)
{
    extern __shared__ float sm[];
    float* xs = sm;              // [ci][row][col] : Cch x HALO_H x HALO_W
    float* ws = sm + XS_ELEMS;   // [ci*9+tap][co] stride WS_STRIDE

    const int bx  = blockIdx.x;          // 0..7   (W tiles)
    const int by  = blockIdx.y;          // 0..15  (H tiles)
    const int bb  = blockIdx.z;          // 0..15  (batch)
    const int tid = threadIdx.x;

    const int x0 = bx * TILE_W;
    const int y0 = by * TILE_H;

    // ---- load weights, transposed to [ci*9+tap][co] ----
    #pragma unroll 1
    for (int i = tid; i < Cch * Cch * 9; i += THREADS) {
        int co  = i / (Cch * 9);
        int rem = i - co * (Cch * 9);    // ci*9 + tap
        ws[rem * WS_STRIDE + co] = w[i];
    }

    // ---- load input tile (x for pass1, h for pass2) with zero halo/pad ----
    const float* inb = (SECOND ? g_h : x) + (size_t)bb * Cch * Himg * Wimg;
    #pragma unroll 1
    for (int i = tid; i < XS_ELEMS; i += THREADS) {
        int ci = i / (HALO_H * HALO_W);
        int r  = (i / HALO_W) % HALO_H;
        int c  = i % HALO_W;
        int gy = y0 + r - 1;
        int gx = x0 + c - 1;
        float v = 0.0f;
        if ((unsigned)gy < (unsigned)Himg && (unsigned)gx < (unsigned)Wimg)
            v = inb[(size_t)ci * (Himg * Wimg) + gy * Wimg + gx];
        xs[i] = v;
    }
    __syncthreads();

    // ---- thread tile: 4 output channels x 8 pixels, f32x2-packed over co ----
    const int cg  = tid & 7;         // co group (8 groups of 4)
    const int pg  = tid >> 3;        // pixel group (64 groups of 8)
    const int r   = pg >> 2;         // tile row 0..15
    const int cb  = (pg & 3) * 8;    // tile col base 0/8/16/24
    const int co0 = cg * 4;

    // accp[p][j] = { acc[co0+2p][j], acc[co0+2p+1][j] }
    unsigned long long accp[2][8];
    #pragma unroll
    for (int p = 0; p < 2; p++)
        #pragma unroll
        for (int j = 0; j < 8; j++)
            accp[p][j] = 0ULL;

    #pragma unroll 2
    for (int ci = 0; ci < Cch; ci++) {
        const float* xci = xs + ci * (HALO_H * HALO_W);
        #pragma unroll
        for (int dy = 0; dy < 3; dy++) {
            // 12 floats (16B-aligned, 3x LDS.128); only [0..9] used
            const float4* xr4 = reinterpret_cast<const float4*>(
                xci + (r + dy) * HALO_W + cb);
            float4 a0 = xr4[0], a1 = xr4[1], a2 = xr4[2];
            float xv[12] = {a0.x, a0.y, a0.z, a0.w,
                            a1.x, a1.y, a1.z, a1.w,
                            a2.x, a2.y, a2.z, a2.w};

            unsigned long long xd[10];
            #pragma unroll
            for (int k = 0; k < 10; k++) xd[k] = pack2_dup(xv[k]);

            #pragma unroll
            for (int dx = 0; dx < 3; dx++) {
                // {w[co0],w[co0+1]} and {w[co0+2],w[co0+3]} via one LDS.128
                const ulonglong2* wp2 = reinterpret_cast<const ulonglong2*>(
                    ws + (ci * 9 + dy * 3 + dx) * WS_STRIDE + co0);
                ulonglong2 wv = *wp2;
                #pragma unroll
                for (int j = 0; j < 8; j++) {
                    fma2(accp[0][j], wv.x, xd[dx + j]);
                    fma2(accp[1][j], wv.y, xd[dx + j]);
                }
            }
        }
    }

    // ---- unpack ----
    float acc[4][8];
    #pragma unroll
    for (int p = 0; p < 2; p++)
        #pragma unroll
        for (int j = 0; j < 8; j++)
            unpack2(acc[2 * p][j], acc[2 * p + 1][j], accp[p][j]);

    // ---- epilogue: bias, gate, relu, (+residual), store ----
    const int oy = y0 + r;
    const int ox = x0 + cb;
    float* dst = SECOND ? out : g_h;

    #pragma unroll
    for (int a = 0; a < 4; a++) {
        int co = co0 + a;
        float bi = bias[co];
        float g  = gate[bb * Cch + co];
        g = (g > 0.0f) ? g : 0.0f;

        size_t base = (((size_t)bb * Cch + co) * Himg + oy) * Wimg + ox;

        float t[8];
        #pragma unroll
        for (int j = 0; j < 8; j++) {
            float v = (acc[a][j] + bi) * g;
            t[j] = (v > 0.0f) ? v : 0.0f;
        }

        if (SECOND) {
            const float4* rx = reinterpret_cast<const float4*>(x + base);
            float4 r0 = rx[0], r1 = rx[1];
            t[0] += r0.x; t[1] += r0.y; t[2] += r0.z; t[3] += r0.w;
            t[4] += r1.x; t[5] += r1.y; t[6] += r1.z; t[7] += r1.w;
        }

        float4* op = reinterpret_cast<float4*>(dst + base);
        op[0] = make_float4(t[0], t[1], t[2], t[3]);
        op[1] = make_float4(t[4], t[5], t[6], t[7]);
    }
}

extern "C" void kernel_launch(void* const* d_in, const int* in_sizes, int n_in,
                              void* d_out, int out_size)
{
    const float* x    = (const float*)d_in[0];
    const float* gate = (const float*)d_in[1];
    const float* w1   = (const float*)d_in[2];
    const float* b1   = (const float*)d_in[3];
    const float* w2   = (const float*)d_in[4];
    const float* b2   = (const float*)d_in[5];
    float*       out  = (float*)d_out;
    (void)in_sizes; (void)n_in; (void)out_size;

    cudaFuncSetAttribute(moe_conv_kernel<false>,
                         cudaFuncAttributeMaxDynamicSharedMemorySize, SMEM_BYTES);
    cudaFuncSetAttribute(moe_conv_kernel<true>,
                         cudaFuncAttributeMaxDynamicSharedMemorySize, SMEM_BYTES);

    dim3 grid(Wimg / TILE_W, Himg / TILE_H, Bsz);   // 8 x 16 x 16 = 2048 CTAs

    // pass 1: h = relu((conv(x,w1)+b1)*g)   -> g_h
    moe_conv_kernel<false><<<grid, THREADS, SMEM_BYTES>>>(x, w1, b1, gate, nullptr);
    // pass 2: out = relu((conv(h,w2)+b2)*g) + x
    moe_conv_kernel<true><<<grid, THREADS, SMEM_BYTES>>>(x, w2, b2, gate, out);
}